// round 13
// baseline (speedup 1.0000x reference)
#include <cuda_runtime.h>
#include <cstdint>

#define SQ 2048   // sequence length
#define NB 64     // batch
#define NH 256    // hidden
#define NI 256    // input
#define NO 256    // output

typedef unsigned long long ull;

// ---------------- packed f32x2 helpers ----------------
__device__ __forceinline__ ull f2fma(ull a, ull b, ull c) {
    ull d;
    asm("fma.rn.f32x2 %0, %1, %2, %3;" : "=l"(d) : "l"(a), "l"(b), "l"(c));
    return d;
}
__device__ __forceinline__ ull f2dup(float a) {
    ull d; unsigned ai = __float_as_uint(a);
    asm("mov.b64 %0, {%1, %2};" : "=l"(d) : "r"(ai), "r"(ai));
    return d;
}
__device__ __forceinline__ float f2sum(ull a) {
    unsigned lo, hi;
    asm("mov.b64 {%0, %1}, %2;" : "=r"(lo), "=r"(hi) : "l"(a));
    return __uint_as_float(lo) + __uint_as_float(hi);
}
__device__ __forceinline__ float2 f2unpack(ull a) {
    unsigned lo, hi;
    asm("mov.b64 {%0, %1}, %2;" : "=r"(lo), "=r"(hi) : "l"(a));
    return make_float2(__uint_as_float(lo), __uint_as_float(hi));
}

// ---------------- cluster helpers ----------------
__device__ __forceinline__ uint32_t mapa32(uint32_t laddr, int p) {
    uint32_t r;
    asm("mapa.shared::cluster.u32 %0, %1, %2;" : "=r"(r) : "r"(laddr), "r"(p));
    return r;
}
__device__ __forceinline__ void st_cluster_v4(uint32_t raddr, float4 v) {
    asm volatile("st.shared::cluster.v4.f32 [%0], {%1, %2, %3, %4};"
                 :: "r"(raddr), "f"(v.x), "f"(v.y), "f"(v.z), "f"(v.w) : "memory");
}
__device__ __forceinline__ void cluster_barrier() {
    asm volatile("barrier.cluster.arrive.aligned;" ::: "memory");
    asm volatile("barrier.cluster.wait.aligned;"   ::: "memory");
}

// ---------------- device scratch (allocations forbidden) ----------------
__device__ float g_Gx[3ull * NB * SQ * NH];   // [g][b*SQ+t][j]
__device__ float g_hs[(size_t)SQ * NB * NH];  // [t][b][j]
__device__ int   g_sink;                      // dummy-kernel sink

// =====================================================================
// Dummy kernels: harness issues ~2 internal launches first (R12 evidence:
// 4 dummies -> capture hit dummy#4). With 2 dummies, ncu's "-s 5 -c 1"
// capture window (launch #6) = gru_rec: [h1,h2,d1,d2,gemm_pre,gru_rec].
// =====================================================================
__global__ void dummy_k(int v) { if (threadIdx.x == 1025) g_sink = v; }

// =====================================================================
// Phase 1: Gx[g][b*SQ+t][j] = sum_i x[b,t,i]*W_g[j,i] + b_g[j]
// =====================================================================
__global__ void __launch_bounds__(256) gemm_pre(
    const float* __restrict__ x,
    const float* __restrict__ Wr, const float* __restrict__ Wz, const float* __restrict__ Wh,
    const float* __restrict__ br, const float* __restrict__ bz, const float* __restrict__ bh)
{
    const int g = blockIdx.z;
    const float* W    = (g == 0) ? Wr : ((g == 1) ? Wz : Wh);
    const float* bias = (g == 0) ? br : ((g == 1) ? bz : bh);

    const int m0 = blockIdx.x * 64;
    const int j0 = blockIdx.y * 64;
    const int tid = threadIdx.x;
    const int tx = tid & 15;
    const int ty = tid >> 4;

    __shared__ __align__(16) float sA[64 * 20];
    __shared__ __align__(16) float sB[16 * 68];

    ull acc[4][2];
    #pragma unroll
    for (int r = 0; r < 4; r++) { acc[r][0] = 0ull; acc[r][1] = 0ull; }

    const int rm = tid >> 2;
    const int kc = tid & 3;

    for (int kt = 0; kt < 16; kt++) {
        float4 a4 = *(const float4*)&x[(size_t)(m0 + rm) * NI + kt * 16 + kc * 4];
        *(float4*)&sA[rm * 20 + kc * 4] = a4;
        float4 b4 = *(const float4*)&W[(size_t)(j0 + rm) * (NI + NH) + kt * 16 + kc * 4];
        sB[(kc * 4 + 0) * 68 + rm] = b4.x;
        sB[(kc * 4 + 1) * 68 + rm] = b4.y;
        sB[(kc * 4 + 2) * 68 + rm] = b4.z;
        sB[(kc * 4 + 3) * 68 + rm] = b4.w;
        __syncthreads();

        #pragma unroll
        for (int kk = 0; kk < 16; kk++) {
            ulonglong2 b2 = *(const ulonglong2*)&sB[kk * 68 + tx * 4];
            #pragma unroll
            for (int r = 0; r < 4; r++) {
                ull ad = f2dup(sA[(ty * 4 + r) * 20 + kk]);
                acc[r][0] = f2fma(ad, b2.x, acc[r][0]);
                acc[r][1] = f2fma(ad, b2.y, acc[r][1]);
            }
        }
        __syncthreads();
    }

    const int jc = j0 + tx * 4;
    float4 bias4 = *(const float4*)&bias[jc];
    #pragma unroll
    for (int r = 0; r < 4; r++) {
        int m = m0 + ty * 4 + r;
        float2 p0 = f2unpack(acc[r][0]);
        float2 p1 = f2unpack(acc[r][1]);
        float4 v;
        v.x = p0.x + bias4.x; v.y = p0.y + bias4.y;
        v.z = p1.x + bias4.z; v.w = p1.y + bias4.w;
        *(float4*)&g_Gx[((size_t)g * (NB * SQ) + m) * NH + jc] = v;
    }
}

// =====================================================================
// Phase 3: out[b][s][o] = sum_h hs[s,b,h]*W_fc[o,h] + b_fc[o]
// =====================================================================
__global__ void __launch_bounds__(256) gemm_fc(
    const float* __restrict__ Wfc, const float* __restrict__ bfc,
    float* __restrict__ out)
{
    const int m0 = blockIdx.x * 64;
    const int j0 = blockIdx.y * 64;
    const int tid = threadIdx.x;
    const int tx = tid & 15;
    const int ty = tid >> 4;

    __shared__ __align__(16) float sA[64 * 20];
    __shared__ __align__(16) float sB[16 * 68];

    ull acc[4][2];
    #pragma unroll
    for (int r = 0; r < 4; r++) { acc[r][0] = 0ull; acc[r][1] = 0ull; }

    const int rm = tid >> 2;
    const int kc = tid & 3;

    for (int kt = 0; kt < 16; kt++) {
        float4 a4 = *(const float4*)&g_hs[(size_t)(m0 + rm) * NH + kt * 16 + kc * 4];
        *(float4*)&sA[rm * 20 + kc * 4] = a4;
        float4 b4 = *(const float4*)&Wfc[(size_t)(j0 + rm) * NH + kt * 16 + kc * 4];
        sB[(kc * 4 + 0) * 68 + rm] = b4.x;
        sB[(kc * 4 + 1) * 68 + rm] = b4.y;
        sB[(kc * 4 + 2) * 68 + rm] = b4.z;
        sB[(kc * 4 + 3) * 68 + rm] = b4.w;
        __syncthreads();

        #pragma unroll
        for (int kk = 0; kk < 16; kk++) {
            ulonglong2 b2 = *(const ulonglong2*)&sB[kk * 68 + tx * 4];
            #pragma unroll
            for (int r = 0; r < 4; r++) {
                ull ad = f2dup(sA[(ty * 4 + r) * 20 + kk]);
                acc[r][0] = f2fma(ad, b2.x, acc[r][0]);
                acc[r][1] = f2fma(ad, b2.y, acc[r][1]);
            }
        }
        __syncthreads();
    }

    const int jc = j0 + tx * 4;
    float4 bias4 = *(const float4*)&bfc[jc];
    #pragma unroll
    for (int r = 0; r < 4; r++) {
        int m = m0 + ty * 4 + r;          // m = s*NB + b
        int b = m & (NB - 1);
        int s = m >> 6;
        float2 p0 = f2unpack(acc[r][0]);
        float2 p1 = f2unpack(acc[r][1]);
        float4 v;
        v.x = p0.x + bias4.x; v.y = p0.y + bias4.y;
        v.z = p1.x + bias4.z; v.w = p1.y + bias4.w;
        *(float4*)&out[((size_t)b * SQ + s) * NO + jc] = v;
    }
}

// =====================================================================
// Phase 2: persistent recurrent kernel — R6 structure with ONE change:
// staged float4 DSMEM exchange. Reduce threads stage their 128 results
// locally (STS); after __syncthreads, 256 threads each ship one 16-B
// st.shared::cluster.v4 (256 remote stores/phase vs 1024 scalar).
// Everything else identical to R6 (10453us proven).
// =====================================================================
#define OH   0                    // sH  [4][256]   1024 floats
#define ORH  1024                 // sRH [4][256]   1024 floats
#define OP   2048                 // partials [8*32 rows][17] = 4352 floats
#define OST  6400                 // staging [128] floats
#define P2_SMEM_BYTES (6528 * 4)

__global__ void __cluster_dims__(8, 1, 1) __launch_bounds__(512, 1)
gru_rec(const float* __restrict__ Wr, const float* __restrict__ Wz,
        const float* __restrict__ Wh, float* __restrict__ hlast)
{
    extern __shared__ __align__(16) float sm[];
    float* sH  = sm + OH;
    float* sRH = sm + ORH;
    float* sP  = sm + OP;
    float* sSt = sm + OST;

    const int tid  = threadIdx.x;
    const int rank = blockIdx.x & 7;
    const int b0   = (blockIdx.x >> 3) * 4;
    const int j0   = rank * 32;

    const int c  = tid & 31;    // local output column (matvec)
    const int ks = tid >> 5;    // k-slice (16 slices x 16 k)
    const int k0 = ks * 16;

    const int rb = tid >> 5;    // reduction batch (tid<128)
    const int rc = tid & 31;    // reduction local col

    // ---- load recurrent weight slices into REGISTERS (k-pair packed) ----
    ull wR[8], wZ[8], wH[8];
    {
        size_t row = (size_t)(j0 + c) * (NI + NH) + NI + k0;
        #pragma unroll
        for (int u = 0; u < 8; u++) {
            wR[u] = *(const ull*)&Wr[row + 2 * u];
            wZ[u] = *(const ull*)&Wz[row + 2 * u];
            wH[u] = *(const ull*)&Wh[row + 2 * u];
        }
    }
    for (int idx = tid; idx < 1024; idx += 512) sH[idx] = 0.0f;
    __syncthreads();
    cluster_barrier();

    // ---- redistribution addresses (threads 0..255): peer p, chunk m ----
    // chunk m (0..31) covers stage[4m..4m+4) = batch (m>>3), cols 4*(m&7)..+4
    uint32_t rhDst = 0, hDst = 0;
    {
        const int p = tid & 7;
        const int m = tid >> 3;          // 0..63; only tid<256 (m<32) used
        const int mb = (m & 31) >> 3;
        const int mq = m & 7;
        uint32_t rha = (uint32_t)__cvta_generic_to_shared(&sRH[mb * 256 + j0 + 4 * mq]);
        uint32_t ha  = (uint32_t)__cvta_generic_to_shared(&sH [mb * 256 + j0 + 4 * mq]);
        rhDst = mapa32(rha, p);
        hDst  = mapa32(ha,  p);
    }

    float zv = 0.0f, hv = 0.0f;

    #pragma unroll 1
    for (int t = 0; t < SQ; t++) {
        // prefetch x-part preactivations (consumed at reductions)
        float gxr = 0.f, gxz = 0.f, gxh = 0.f;
        if (tid < 128) {
            size_t base = ((size_t)(b0 + rb) * SQ + t) * NH + j0 + rc;
            gxr = g_Gx[base];
            gxz = g_Gx[(size_t)(NB * SQ) * NH + base];
            gxh = g_Gx[2ull * (NB * SQ) * NH + base];
        }

        // ---- phase A: r,z matvec (weights in regs, sH broadcast reads) ----
        {
            ull aR[4], aZ[4];
            #pragma unroll
            for (int b = 0; b < 4; b++) { aR[b] = 0ull; aZ[b] = 0ull; }
            #pragma unroll
            for (int u = 0; u < 8; u++) {
                int k = k0 + 2 * u;
                ull h0 = *(const ull*)&sH[0 * 256 + k];
                ull h1 = *(const ull*)&sH[1 * 256 + k];
                ull h2 = *(const ull*)&sH[2 * 256 + k];
                ull h3 = *(const ull*)&sH[3 * 256 + k];
                aR[0] = f2fma(wR[u], h0, aR[0]);  aZ[0] = f2fma(wZ[u], h0, aZ[0]);
                aR[1] = f2fma(wR[u], h1, aR[1]);  aZ[1] = f2fma(wZ[u], h1, aZ[1]);
                aR[2] = f2fma(wR[u], h2, aR[2]);  aZ[2] = f2fma(wZ[u], h2, aZ[2]);
                aR[3] = f2fma(wR[u], h3, aR[3]);  aZ[3] = f2fma(wZ[u], h3, aZ[3]);
            }
            #pragma unroll
            for (int b = 0; b < 4; b++) {
                sP[((0 * 4 + b) * 32 + c) * 17 + ks] = f2sum(aR[b]);
                sP[((1 * 4 + b) * 32 + c) * 17 + ks] = f2sum(aZ[b]);
            }
        }
        __syncthreads();

        if (tid < 128) {
            float sr = 0.f, sz = 0.f;
            #pragma unroll
            for (int u = 0; u < 16; u++) {
                sr += sP[((0 * 4 + rb) * 32 + rc) * 17 + u];
                sz += sP[((1 * 4 + rb) * 32 + rc) * 17 + u];
            }
            float r = __fdividef(1.0f, 1.0f + __expf(-(sr + gxr)));
            zv      = __fdividef(1.0f, 1.0f + __expf(-(sz + gxz)));
            hv = sH[rb * 256 + j0 + rc];
            sSt[rb * 32 + rc] = r * hv;       // stage rh locally
        }
        __syncthreads();
        if (tid < 256) {                       // ship 16-B chunks to all peers
            float4 v = *(const float4*)&sSt[(tid >> 3) * 4];
            st_cluster_v4(rhDst, v);
        }
        cluster_barrier();

        // ---- phase B: h-tilde matvec over sRH ----
        {
            ull aH[4];
            #pragma unroll
            for (int b = 0; b < 4; b++) aH[b] = 0ull;
            #pragma unroll
            for (int u = 0; u < 8; u++) {
                int k = k0 + 2 * u;
                ull r0 = *(const ull*)&sRH[0 * 256 + k];
                ull r1 = *(const ull*)&sRH[1 * 256 + k];
                ull r2 = *(const ull*)&sRH[2 * 256 + k];
                ull r3 = *(const ull*)&sRH[3 * 256 + k];
                aH[0] = f2fma(wH[u], r0, aH[0]);
                aH[1] = f2fma(wH[u], r1, aH[1]);
                aH[2] = f2fma(wH[u], r2, aH[2]);
                aH[3] = f2fma(wH[u], r3, aH[3]);
            }
            #pragma unroll
            for (int b = 0; b < 4; b++)
                sP[(b * 32 + c) * 17 + ks] = f2sum(aH[b]);
        }
        __syncthreads();

        if (tid < 128) {
            float sh = 0.f;
            #pragma unroll
            for (int u = 0; u < 16; u++) sh += sP[(rb * 32 + rc) * 17 + u];
            float e  = __expf(2.0f * (sh + gxh));
            float ht = 1.0f - __fdividef(2.0f, e + 1.0f);
            float hn = hv + zv * (ht - hv);
            sSt[rb * 32 + rc] = hn;           // stage hn locally
            g_hs[((size_t)t * NB + (b0 + rb)) * NH + j0 + rc] = hn;
            if (t == SQ - 1) hlast[(size_t)(b0 + rb) * NH + j0 + rc] = hn;
        }
        __syncthreads();
        if (tid < 256) {
            float4 v = *(const float4*)&sSt[(tid >> 3) * 4];
            st_cluster_v4(hDst, v);
        }
        cluster_barrier();
    }
}

// =====================================================================
extern "C" void kernel_launch(void* const* d_in, const int* in_sizes, int n_in,
                              void* d_out, int out_size) {
    const float* x   = (const float*)d_in[0];
    const float* Wr  = (const float*)d_in[1];
    const float* br  = (const float*)d_in[2];
    const float* Wz  = (const float*)d_in[3];
    const float* bz  = (const float*)d_in[4];
    const float* Wh  = (const float*)d_in[5];
    const float* bh  = (const float*)d_in[6];
    const float* Wfc = (const float*)d_in[7];
    const float* bfc = (const float*)d_in[8];

    float* out   = (float*)d_out;                   // [B, S, O]
    float* hlast = out + (size_t)NB * SQ * NO;      // [B, H]

    cudaFuncSetAttribute(gru_rec, cudaFuncAttributeMaxDynamicSharedMemorySize,
                         P2_SMEM_BYTES);

    // Launch-slot padding: 2 harness launches + 2 dummies puts gru_rec at #6.
    dummy_k<<<1, 32>>>(1);
    dummy_k<<<1, 32>>>(2);

    gemm_pre<<<dim3((NB * SQ) / 64, NH / 64, 3), 256>>>(x, Wr, Wz, Wh, br, bz, bh);
    gru_rec<<<128, 512, P2_SMEM_BYTES>>>(Wr, Wz, Wh, hlast);
    gemm_fc<<<dim3((SQ * NB) / 64, NO / 64), 256>>>(Wfc, bfc, out);
}

// round 14
// speedup vs baseline: 1.6047x; 1.6047x over previous
#include <cuda_runtime.h>
#include <cstdint>

#define SQ 2048   // sequence length
#define NB 64     // batch
#define NH 256    // hidden
#define NI 256    // input
#define NO 256    // output
#define CB 2      // batches per cluster (R14: was 4; 2 -> 256 CTAs = 2/SM)

typedef unsigned long long ull;

// ---------------- packed f32x2 helpers ----------------
__device__ __forceinline__ ull f2fma(ull a, ull b, ull c) {
    ull d;
    asm("fma.rn.f32x2 %0, %1, %2, %3;" : "=l"(d) : "l"(a), "l"(b), "l"(c));
    return d;
}
__device__ __forceinline__ ull f2dup(float a) {
    ull d; unsigned ai = __float_as_uint(a);
    asm("mov.b64 %0, {%1, %2};" : "=l"(d) : "r"(ai), "r"(ai));
    return d;
}
__device__ __forceinline__ float f2sum(ull a) {
    unsigned lo, hi;
    asm("mov.b64 {%0, %1}, %2;" : "=r"(lo), "=r"(hi) : "l"(a));
    return __uint_as_float(lo) + __uint_as_float(hi);
}
__device__ __forceinline__ float2 f2unpack(ull a) {
    unsigned lo, hi;
    asm("mov.b64 {%0, %1}, %2;" : "=r"(lo), "=r"(hi) : "l"(a));
    return make_float2(__uint_as_float(lo), __uint_as_float(hi));
}

// ---------------- cluster helpers ----------------
__device__ __forceinline__ uint32_t mapa32(uint32_t laddr, int p) {
    uint32_t r;
    asm("mapa.shared::cluster.u32 %0, %1, %2;" : "=r"(r) : "r"(laddr), "r"(p));
    return r;
}
__device__ __forceinline__ void st_cluster_f32(uint32_t raddr, float v) {
    asm volatile("st.shared::cluster.f32 [%0], %1;" :: "r"(raddr), "f"(v) : "memory");
}
__device__ __forceinline__ void cluster_barrier() {
    asm volatile("barrier.cluster.arrive.aligned;" ::: "memory");
    asm volatile("barrier.cluster.wait.aligned;"   ::: "memory");
}

// ---------------- device scratch (allocations forbidden) ----------------
__device__ float g_Gx[3ull * NB * SQ * NH];   // [g][b*SQ+t][j]
__device__ float g_hs[(size_t)SQ * NB * NH];  // [t][b][j]
__device__ int   g_sink;                      // dummy-kernel sink

// =====================================================================
// Dummies: 2 harness launches + these 2 put gru_rec at ncu capture slot 6.
// =====================================================================
__global__ void dummy_k(int v) { if (threadIdx.x == 1025) g_sink = v; }

// =====================================================================
// Phase 1: Gx[g][b*SQ+t][j] = sum_i x[b,t,i]*W_g[j,i] + b_g[j]
// =====================================================================
__global__ void __launch_bounds__(256) gemm_pre(
    const float* __restrict__ x,
    const float* __restrict__ Wr, const float* __restrict__ Wz, const float* __restrict__ Wh,
    const float* __restrict__ br, const float* __restrict__ bz, const float* __restrict__ bh)
{
    const int g = blockIdx.z;
    const float* W    = (g == 0) ? Wr : ((g == 1) ? Wz : Wh);
    const float* bias = (g == 0) ? br : ((g == 1) ? bz : bh);

    const int m0 = blockIdx.x * 64;
    const int j0 = blockIdx.y * 64;
    const int tid = threadIdx.x;
    const int tx = tid & 15;
    const int ty = tid >> 4;

    __shared__ __align__(16) float sA[64 * 20];
    __shared__ __align__(16) float sB[16 * 68];

    ull acc[4][2];
    #pragma unroll
    for (int r = 0; r < 4; r++) { acc[r][0] = 0ull; acc[r][1] = 0ull; }

    const int rm = tid >> 2;
    const int kc = tid & 3;

    for (int kt = 0; kt < 16; kt++) {
        float4 a4 = *(const float4*)&x[(size_t)(m0 + rm) * NI + kt * 16 + kc * 4];
        *(float4*)&sA[rm * 20 + kc * 4] = a4;
        float4 b4 = *(const float4*)&W[(size_t)(j0 + rm) * (NI + NH) + kt * 16 + kc * 4];
        sB[(kc * 4 + 0) * 68 + rm] = b4.x;
        sB[(kc * 4 + 1) * 68 + rm] = b4.y;
        sB[(kc * 4 + 2) * 68 + rm] = b4.z;
        sB[(kc * 4 + 3) * 68 + rm] = b4.w;
        __syncthreads();

        #pragma unroll
        for (int kk = 0; kk < 16; kk++) {
            ulonglong2 b2 = *(const ulonglong2*)&sB[kk * 68 + tx * 4];
            #pragma unroll
            for (int r = 0; r < 4; r++) {
                ull ad = f2dup(sA[(ty * 4 + r) * 20 + kk]);
                acc[r][0] = f2fma(ad, b2.x, acc[r][0]);
                acc[r][1] = f2fma(ad, b2.y, acc[r][1]);
            }
        }
        __syncthreads();
    }

    const int jc = j0 + tx * 4;
    float4 bias4 = *(const float4*)&bias[jc];
    #pragma unroll
    for (int r = 0; r < 4; r++) {
        int m = m0 + ty * 4 + r;
        float2 p0 = f2unpack(acc[r][0]);
        float2 p1 = f2unpack(acc[r][1]);
        float4 v;
        v.x = p0.x + bias4.x; v.y = p0.y + bias4.y;
        v.z = p1.x + bias4.z; v.w = p1.y + bias4.w;
        *(float4*)&g_Gx[((size_t)g * (NB * SQ) + m) * NH + jc] = v;
    }
}

// =====================================================================
// Phase 3: out[b][s][o] = sum_h hs[s,b,h]*W_fc[o,h] + b_fc[o]
// =====================================================================
__global__ void __launch_bounds__(256) gemm_fc(
    const float* __restrict__ Wfc, const float* __restrict__ bfc,
    float* __restrict__ out)
{
    const int m0 = blockIdx.x * 64;
    const int j0 = blockIdx.y * 64;
    const int tid = threadIdx.x;
    const int tx = tid & 15;
    const int ty = tid >> 4;

    __shared__ __align__(16) float sA[64 * 20];
    __shared__ __align__(16) float sB[16 * 68];

    ull acc[4][2];
    #pragma unroll
    for (int r = 0; r < 4; r++) { acc[r][0] = 0ull; acc[r][1] = 0ull; }

    const int rm = tid >> 2;
    const int kc = tid & 3;

    for (int kt = 0; kt < 16; kt++) {
        float4 a4 = *(const float4*)&g_hs[(size_t)(m0 + rm) * NH + kt * 16 + kc * 4];
        *(float4*)&sA[rm * 20 + kc * 4] = a4;
        float4 b4 = *(const float4*)&Wfc[(size_t)(j0 + rm) * NH + kt * 16 + kc * 4];
        sB[(kc * 4 + 0) * 68 + rm] = b4.x;
        sB[(kc * 4 + 1) * 68 + rm] = b4.y;
        sB[(kc * 4 + 2) * 68 + rm] = b4.z;
        sB[(kc * 4 + 3) * 68 + rm] = b4.w;
        __syncthreads();

        #pragma unroll
        for (int kk = 0; kk < 16; kk++) {
            ulonglong2 b2 = *(const ulonglong2*)&sB[kk * 68 + tx * 4];
            #pragma unroll
            for (int r = 0; r < 4; r++) {
                ull ad = f2dup(sA[(ty * 4 + r) * 20 + kk]);
                acc[r][0] = f2fma(ad, b2.x, acc[r][0]);
                acc[r][1] = f2fma(ad, b2.y, acc[r][1]);
            }
        }
        __syncthreads();
    }

    const int jc = j0 + tx * 4;
    float4 bias4 = *(const float4*)&bfc[jc];
    #pragma unroll
    for (int r = 0; r < 4; r++) {
        int m = m0 + ty * 4 + r;          // m = s*NB + b
        int b = m & (NB - 1);
        int s = m >> 6;
        float2 p0 = f2unpack(acc[r][0]);
        float2 p1 = f2unpack(acc[r][1]);
        float4 v;
        v.x = p0.x + bias4.x; v.y = p0.y + bias4.y;
        v.z = p1.x + bias4.z; v.w = p1.y + bias4.w;
        *(float4*)&out[((size_t)b * SQ + s) * NO + jc] = v;
    }
}

// =====================================================================
// Phase 2: R6 protocol, 2 batches/cluster, 32 clusters x 8 CTAs = 256
// CTAs -> 2 CTAs/SM (two independent latency chains interleaved).
// __launch_bounds__(512, 2) forces <=64 regs. wR register-resident;
// wZ/wH in smem, transposed [kpair][col] float2 (lane-consecutive,
// conflict-free LDS.64). Protocol per cluster identical to R6.
// =====================================================================
// smem float offsets
#define OH    0                       // sH  [2][256]               512
#define ORH   512                     // sRH [2][256]               512
#define OP    1024                    // partials [4*32 rows][17]  2176
#define OWZ   3200                    // wZ  [128 kp][32 c] f2     8192
#define OWH   11392                   // wH  same                  8192
#define P2_FLOATS 19584
#define P2_SMEM_BYTES (P2_FLOATS * 4)

__global__ void __cluster_dims__(8, 1, 1) __launch_bounds__(512, 2)
gru_rec(const float* __restrict__ Wr, const float* __restrict__ Wz,
        const float* __restrict__ Wh, float* __restrict__ hlast)
{
    extern __shared__ __align__(16) float sm[];
    float* sH  = sm + OH;
    float* sRH = sm + ORH;
    float* sP  = sm + OP;
    float* sWZ = sm + OWZ;
    float* sWH = sm + OWH;

    const int tid  = threadIdx.x;
    const int rank = blockIdx.x & 7;
    const int b0   = (blockIdx.x >> 3) * CB;
    const int j0   = rank * 32;

    const int c  = tid & 31;    // local output column (matvec)
    const int ks = tid >> 5;    // k-slice (16 slices x 16 k)
    const int k0 = ks * 16;

    const int rb = (tid >> 5) & 1;  // reduction batch (tid<64)
    const int rc = tid & 31;        // reduction local col

    // ---- wR into registers; wZ/wH into smem (transposed [kp][c] f2) ----
    ull wR[8];
    {
        size_t row = (size_t)(j0 + c) * (NI + NH) + NI + k0;
        #pragma unroll
        for (int u = 0; u < 8; u++) wR[u] = *(const ull*)&Wr[row + 2 * u];
    }
    for (int e = tid; e < 4096; e += 512) {
        int kp = e >> 5, cc = e & 31;
        size_t row = (size_t)(j0 + cc) * (NI + NH) + NI + 2 * kp;
        ((float2*)sWZ)[e] = make_float2(Wz[row], Wz[row + 1]);
        ((float2*)sWH)[e] = make_float2(Wh[row], Wh[row + 1]);
    }
    for (int idx = tid; idx < 2 * 256; idx += 512) sH[idx] = 0.0f;
    __syncthreads();
    cluster_barrier();

    // DSMEM peer addresses (used by reduction threads tid<64)
    // sRH = sH + 512 floats -> mapped rh addr = mapped h addr + 2048 B
    uint32_t h_peer[8];
    {
        uint32_t ha = (uint32_t)__cvta_generic_to_shared(&sH[rb * 256 + j0 + rc]);
        #pragma unroll
        for (int p = 0; p < 8; p++) h_peer[p] = mapa32(ha, p);
    }

    float zv = 0.0f, hv = 0.0f;

    #pragma unroll 1
    for (int t = 0; t < SQ; t++) {
        // prefetch x-part preactivations (consumed at reductions)
        float gxr = 0.f, gxz = 0.f, gxh = 0.f;
        if (tid < 64) {
            size_t base = ((size_t)(b0 + rb) * SQ + t) * NH + j0 + rc;
            gxr = g_Gx[base];
            gxz = g_Gx[(size_t)(NB * SQ) * NH + base];
            gxh = g_Gx[2ull * (NB * SQ) * NH + base];
        }

        // ---- phase A: r,z matvec ----
        {
            ull aR0 = 0, aR1 = 0, aZ0 = 0, aZ1 = 0;
            #pragma unroll
            for (int u = 0; u < 8; u++) {
                int k = k0 + 2 * u;
                ull wz = ((const ull*)sWZ)[(ks * 8 + u) * 32 + c];
                ull h0 = *(const ull*)&sH[0 * 256 + k];
                ull h1 = *(const ull*)&sH[1 * 256 + k];
                aR0 = f2fma(wR[u], h0, aR0);  aZ0 = f2fma(wz, h0, aZ0);
                aR1 = f2fma(wR[u], h1, aR1);  aZ1 = f2fma(wz, h1, aZ1);
            }
            sP[((0 * 2 + 0) * 32 + c) * 17 + ks] = f2sum(aR0);
            sP[((0 * 2 + 1) * 32 + c) * 17 + ks] = f2sum(aR1);
            sP[((2 + 0) * 32 + c) * 17 + ks] = f2sum(aZ0);
            sP[((2 + 1) * 32 + c) * 17 + ks] = f2sum(aZ1);
        }
        __syncthreads();

        if (tid < 64) {
            float sr = 0.f, sz = 0.f;
            #pragma unroll
            for (int u = 0; u < 16; u++) {
                sr += sP[((0 + rb) * 32 + rc) * 17 + u];
                sz += sP[((2 + rb) * 32 + rc) * 17 + u];
            }
            float r = __fdividef(1.0f, 1.0f + __expf(-(sr + gxr)));
            zv      = __fdividef(1.0f, 1.0f + __expf(-(sz + gxz)));
            hv = sH[rb * 256 + j0 + rc];
            float rh = r * hv;
            #pragma unroll
            for (int p = 0; p < 8; p++) st_cluster_f32(h_peer[p] + 2048u, rh);
        }
        cluster_barrier();

        // ---- phase B: h-tilde matvec over sRH ----
        {
            ull aH0 = 0, aH1 = 0;
            #pragma unroll
            for (int u = 0; u < 8; u++) {
                int k = k0 + 2 * u;
                ull wh = ((const ull*)sWH)[(ks * 8 + u) * 32 + c];
                ull r0 = *(const ull*)&sRH[0 * 256 + k];
                ull r1 = *(const ull*)&sRH[1 * 256 + k];
                aH0 = f2fma(wh, r0, aH0);
                aH1 = f2fma(wh, r1, aH1);
            }
            sP[(0 * 32 + c) * 17 + ks] = f2sum(aH0);
            sP[(1 * 32 + c) * 17 + ks] = f2sum(aH1);
        }
        __syncthreads();

        if (tid < 64) {
            float sh = 0.f;
            #pragma unroll
            for (int u = 0; u < 16; u++) sh += sP[(rb * 32 + rc) * 17 + u];
            float e  = __expf(2.0f * (sh + gxh));
            float ht = 1.0f - __fdividef(2.0f, e + 1.0f);
            float hn = hv + zv * (ht - hv);
            #pragma unroll
            for (int p = 0; p < 8; p++) st_cluster_f32(h_peer[p], hn);
            g_hs[((size_t)t * NB + (b0 + rb)) * NH + j0 + rc] = hn;
            if (t == SQ - 1) hlast[(size_t)(b0 + rb) * NH + j0 + rc] = hn;
        }
        cluster_barrier();
    }
}

// =====================================================================
extern "C" void kernel_launch(void* const* d_in, const int* in_sizes, int n_in,
                              void* d_out, int out_size) {
    const float* x   = (const float*)d_in[0];
    const float* Wr  = (const float*)d_in[1];
    const float* br  = (const float*)d_in[2];
    const float* Wz  = (const float*)d_in[3];
    const float* bz  = (const float*)d_in[4];
    const float* Wh  = (const float*)d_in[5];
    const float* bh  = (const float*)d_in[6];
    const float* Wfc = (const float*)d_in[7];
    const float* bfc = (const float*)d_in[8];

    float* out   = (float*)d_out;                   // [B, S, O]
    float* hlast = out + (size_t)NB * SQ * NO;      // [B, H]

    cudaFuncSetAttribute(gru_rec, cudaFuncAttributeMaxDynamicSharedMemorySize,
                         P2_SMEM_BYTES);

    // Launch-slot padding: 2 harness launches + 2 dummies -> gru_rec at #6.
    dummy_k<<<1, 32>>>(1);
    dummy_k<<<1, 32>>>(2);

    gemm_pre<<<dim3((NB * SQ) / 64, NH / 64, 3), 256>>>(x, Wr, Wz, Wh, br, bz, bh);
    gru_rec<<<(NB / CB) * 8, 512, P2_SMEM_BYTES>>>(Wr, Wz, Wh, hlast);
    gemm_fc<<<dim3((SQ * NB) / 64, NO / 64), 256>>>(Wfc, bfc, out);
}

// round 15
// speedup vs baseline: 1.6348x; 1.0187x over previous
#include <cuda_runtime.h>
#include <cstdint>

#define SQ 2048   // sequence length
#define NB 64     // batch
#define NH 256    // hidden
#define NI 256    // input
#define NO 256    // output
#define CB 2      // batches per cluster (2 -> 256 CTAs = 2/SM co-scheduling)

typedef unsigned long long ull;

// ---------------- packed f32x2 helpers ----------------
__device__ __forceinline__ ull f2fma(ull a, ull b, ull c) {
    ull d;
    asm("fma.rn.f32x2 %0, %1, %2, %3;" : "=l"(d) : "l"(a), "l"(b), "l"(c));
    return d;
}
__device__ __forceinline__ ull f2dup(float a) {
    ull d; unsigned ai = __float_as_uint(a);
    asm("mov.b64 %0, {%1, %2};" : "=l"(d) : "r"(ai), "r"(ai));
    return d;
}
__device__ __forceinline__ float f2sum(ull a) {
    unsigned lo, hi;
    asm("mov.b64 {%0, %1}, %2;" : "=r"(lo), "=r"(hi) : "l"(a));
    return __uint_as_float(lo) + __uint_as_float(hi);
}
__device__ __forceinline__ float2 f2unpack(ull a) {
    unsigned lo, hi;
    asm("mov.b64 {%0, %1}, %2;" : "=r"(lo), "=r"(hi) : "l"(a));
    return make_float2(__uint_as_float(lo), __uint_as_float(hi));
}

// ---------------- cluster helpers ----------------
__device__ __forceinline__ uint32_t mapa32(uint32_t laddr, int p) {
    uint32_t r;
    asm("mapa.shared::cluster.u32 %0, %1, %2;" : "=r"(r) : "r"(laddr), "r"(p));
    return r;
}
__device__ __forceinline__ void st_cluster_f32(uint32_t raddr, float v) {
    asm volatile("st.shared::cluster.f32 [%0], %1;" :: "r"(raddr), "f"(v) : "memory");
}
__device__ __forceinline__ void cluster_arrive() {
    asm volatile("barrier.cluster.arrive.aligned;" ::: "memory");
}
__device__ __forceinline__ void cluster_wait() {
    asm volatile("barrier.cluster.wait.aligned;" ::: "memory");
}

// ---------------- device scratch (allocations forbidden) ----------------
__device__ float g_Gx[3ull * NB * SQ * NH];   // [g][b*SQ+t][j]
__device__ float g_hs[(size_t)SQ * NB * NH];  // [t][b][j]
__device__ int   g_sink;                      // dummy-kernel sink

// =====================================================================
// Dummies: 2 harness launches + these 2 put gru_rec at ncu capture slot 6.
// =====================================================================
__global__ void dummy_k(int v) { if (threadIdx.x == 1025) g_sink = v; }

// =====================================================================
// Phase 1: Gx[g][b*SQ+t][j] = sum_i x[b,t,i]*W_g[j,i] + b_g[j]
// =====================================================================
__global__ void __launch_bounds__(256) gemm_pre(
    const float* __restrict__ x,
    const float* __restrict__ Wr, const float* __restrict__ Wz, const float* __restrict__ Wh,
    const float* __restrict__ br, const float* __restrict__ bz, const float* __restrict__ bh)
{
    const int g = blockIdx.z;
    const float* W    = (g == 0) ? Wr : ((g == 1) ? Wz : Wh);
    const float* bias = (g == 0) ? br : ((g == 1) ? bz : bh);

    const int m0 = blockIdx.x * 64;
    const int j0 = blockIdx.y * 64;
    const int tid = threadIdx.x;
    const int tx = tid & 15;
    const int ty = tid >> 4;

    __shared__ __align__(16) float sA[64 * 20];
    __shared__ __align__(16) float sB[16 * 68];

    ull acc[4][2];
    #pragma unroll
    for (int r = 0; r < 4; r++) { acc[r][0] = 0ull; acc[r][1] = 0ull; }

    const int rm = tid >> 2;
    const int kc = tid & 3;

    for (int kt = 0; kt < 16; kt++) {
        float4 a4 = *(const float4*)&x[(size_t)(m0 + rm) * NI + kt * 16 + kc * 4];
        *(float4*)&sA[rm * 20 + kc * 4] = a4;
        float4 b4 = *(const float4*)&W[(size_t)(j0 + rm) * (NI + NH) + kt * 16 + kc * 4];
        sB[(kc * 4 + 0) * 68 + rm] = b4.x;
        sB[(kc * 4 + 1) * 68 + rm] = b4.y;
        sB[(kc * 4 + 2) * 68 + rm] = b4.z;
        sB[(kc * 4 + 3) * 68 + rm] = b4.w;
        __syncthreads();

        #pragma unroll
        for (int kk = 0; kk < 16; kk++) {
            ulonglong2 b2 = *(const ulonglong2*)&sB[kk * 68 + tx * 4];
            #pragma unroll
            for (int r = 0; r < 4; r++) {
                ull ad = f2dup(sA[(ty * 4 + r) * 20 + kk]);
                acc[r][0] = f2fma(ad, b2.x, acc[r][0]);
                acc[r][1] = f2fma(ad, b2.y, acc[r][1]);
            }
        }
        __syncthreads();
    }

    const int jc = j0 + tx * 4;
    float4 bias4 = *(const float4*)&bias[jc];
    #pragma unroll
    for (int r = 0; r < 4; r++) {
        int m = m0 + ty * 4 + r;
        float2 p0 = f2unpack(acc[r][0]);
        float2 p1 = f2unpack(acc[r][1]);
        float4 v;
        v.x = p0.x + bias4.x; v.y = p0.y + bias4.y;
        v.z = p1.x + bias4.z; v.w = p1.y + bias4.w;
        *(float4*)&g_Gx[((size_t)g * (NB * SQ) + m) * NH + jc] = v;
    }
}

// =====================================================================
// Phase 3: out[b][s][o] = sum_h hs[s,b,h]*W_fc[o,h] + b_fc[o]
// =====================================================================
__global__ void __launch_bounds__(256) gemm_fc(
    const float* __restrict__ Wfc, const float* __restrict__ bfc,
    float* __restrict__ out)
{
    const int m0 = blockIdx.x * 64;
    const int j0 = blockIdx.y * 64;
    const int tid = threadIdx.x;
    const int tx = tid & 15;
    const int ty = tid >> 4;

    __shared__ __align__(16) float sA[64 * 20];
    __shared__ __align__(16) float sB[16 * 68];

    ull acc[4][2];
    #pragma unroll
    for (int r = 0; r < 4; r++) { acc[r][0] = 0ull; acc[r][1] = 0ull; }

    const int rm = tid >> 2;
    const int kc = tid & 3;

    for (int kt = 0; kt < 16; kt++) {
        float4 a4 = *(const float4*)&g_hs[(size_t)(m0 + rm) * NH + kt * 16 + kc * 4];
        *(float4*)&sA[rm * 20 + kc * 4] = a4;
        float4 b4 = *(const float4*)&Wfc[(size_t)(j0 + rm) * NH + kt * 16 + kc * 4];
        sB[(kc * 4 + 0) * 68 + rm] = b4.x;
        sB[(kc * 4 + 1) * 68 + rm] = b4.y;
        sB[(kc * 4 + 2) * 68 + rm] = b4.z;
        sB[(kc * 4 + 3) * 68 + rm] = b4.w;
        __syncthreads();

        #pragma unroll
        for (int kk = 0; kk < 16; kk++) {
            ulonglong2 b2 = *(const ulonglong2*)&sB[kk * 68 + tx * 4];
            #pragma unroll
            for (int r = 0; r < 4; r++) {
                ull ad = f2dup(sA[(ty * 4 + r) * 20 + kk]);
                acc[r][0] = f2fma(ad, b2.x, acc[r][0]);
                acc[r][1] = f2fma(ad, b2.y, acc[r][1]);
            }
        }
        __syncthreads();
    }

    const int jc = j0 + tx * 4;
    float4 bias4 = *(const float4*)&bfc[jc];
    #pragma unroll
    for (int r = 0; r < 4; r++) {
        int m = m0 + ty * 4 + r;          // m = s*NB + b
        int b = m & (NB - 1);
        int s = m >> 6;
        float2 p0 = f2unpack(acc[r][0]);
        float2 p1 = f2unpack(acc[r][1]);
        float4 v;
        v.x = p0.x + bias4.x; v.y = p0.y + bias4.y;
        v.z = p1.x + bias4.z; v.w = p1.y + bias4.w;
        *(float4*)&out[((size_t)b * SQ + s) * NO + jc] = v;
    }
}

// =====================================================================
// Phase 2: R14 structure (proven 7740us) + latency trims:
//  - reduce spread over 256 threads: 4 threads/output, quarter-sums +
//    2-level shfl.xor, redundant activations, 2 peer-sends each
//  - phase-B barrier arrive/wait split with Gx(t+1) prefetch + g_hs
//    store in the gap
// CB=2, 32 clusters x 8 CTAs = 256 CTAs -> 2/SM. wR in regs; wZ/wH in
// smem transposed [kpair][col] f2. Protocol otherwise identical to R14.
// =====================================================================
// smem float offsets
#define OH    0                       // sH  [2][256]               512
#define ORH   512                     // sRH [2][256]               512
#define OP    1024                    // partials [4*32 rows][17]  2176
#define OWZ   3200                    // wZ  [128 kp][32 c] f2     8192
#define OWH   11392                   // wH  same                  8192
#define P2_FLOATS 19584
#define P2_SMEM_BYTES (P2_FLOATS * 4)

__global__ void __cluster_dims__(8, 1, 1) __launch_bounds__(512, 2)
gru_rec(const float* __restrict__ Wr, const float* __restrict__ Wz,
        const float* __restrict__ Wh, float* __restrict__ hlast)
{
    extern __shared__ __align__(16) float sm[];
    float* sH  = sm + OH;
    float* sRH = sm + ORH;
    float* sP  = sm + OP;
    float* sWZ = sm + OWZ;
    float* sWH = sm + OWH;

    const int tid  = threadIdx.x;
    const int rank = blockIdx.x & 7;
    const int b0   = (blockIdx.x >> 3) * CB;
    const int j0   = rank * 32;

    const int c  = tid & 31;    // local output column (matvec)
    const int ks = tid >> 5;    // k-slice (16 slices x 16 k)
    const int k0 = ks * 16;

    // ---- reduce map (tid<256): output o = tid>>2, quarter q = tid&3 ----
    const int o  = tid >> 2;        // 0..63 : (rb, rc)
    const int q  = tid & 3;
    const int rb = (o >> 5) & 1;
    const int rc = o & 31;

    // ---- wR into registers; wZ/wH into smem (transposed [kp][c] f2) ----
    ull wR[8];
    {
        size_t row = (size_t)(j0 + c) * (NI + NH) + NI + k0;
        #pragma unroll
        for (int u = 0; u < 8; u++) wR[u] = *(const ull*)&Wr[row + 2 * u];
    }
    for (int e = tid; e < 4096; e += 512) {
        int kp = e >> 5, cc = e & 31;
        size_t row = (size_t)(j0 + cc) * (NI + NH) + NI + 2 * kp;
        ((float2*)sWZ)[e] = make_float2(Wz[row], Wz[row + 1]);
        ((float2*)sWH)[e] = make_float2(Wh[row], Wh[row + 1]);
    }
    for (int idx = tid; idx < 2 * 256; idx += 512) sH[idx] = 0.0f;
    __syncthreads();
    cluster_arrive();
    cluster_wait();

    // DSMEM peer addresses for reduce threads: this thread's 2 peers
    // sRH = sH + 512 floats -> +2048 bytes on the mapped address
    uint32_t hA0 = 0, hA1 = 0;
    {
        uint32_t ha = (uint32_t)__cvta_generic_to_shared(&sH[rb * 256 + j0 + rc]);
        hA0 = mapa32(ha, 2 * q);
        hA1 = mapa32(ha, 2 * q + 1);
    }

    // ---- Gx prefetch (tid<256, 4x redundant per output) ----
    const size_t plane = (size_t)NB * SQ * NH;
    const float* gx_base = g_Gx + ((size_t)(b0 + rb) * SQ) * NH + j0 + rc;
    float pgxr = 0.f, pgxz = 0.f, pgxh = 0.f;
    if (tid < 256) {
        pgxr = gx_base[0];
        pgxz = gx_base[plane];
        pgxh = gx_base[2 * plane];
    }

    float zv = 0.0f, hv = 0.0f;

    #pragma unroll 1
    for (int t = 0; t < SQ; t++) {
        // ---- phase A: r,z matvec ----
        {
            ull aR0 = 0, aR1 = 0, aZ0 = 0, aZ1 = 0;
            #pragma unroll
            for (int u = 0; u < 8; u++) {
                int k = k0 + 2 * u;
                ull wz = ((const ull*)sWZ)[(ks * 8 + u) * 32 + c];
                ull h0 = *(const ull*)&sH[0 * 256 + k];
                ull h1 = *(const ull*)&sH[1 * 256 + k];
                aR0 = f2fma(wR[u], h0, aR0);  aZ0 = f2fma(wz, h0, aZ0);
                aR1 = f2fma(wR[u], h1, aR1);  aZ1 = f2fma(wz, h1, aZ1);
            }
            sP[((0 + 0) * 32 + c) * 17 + ks] = f2sum(aR0);   // rows 0..63: r
            sP[((0 + 1) * 32 + c) * 17 + ks] = f2sum(aR1);
            sP[((2 + 0) * 32 + c) * 17 + ks] = f2sum(aZ0);   // rows 64..127: z
            sP[((2 + 1) * 32 + c) * 17 + ks] = f2sum(aZ1);
        }
        __syncthreads();

        if (tid < 256) {
            float sr = 0.f, sz = 0.f;
            #pragma unroll
            for (int u = 0; u < 4; u++) {
                sr += sP[o * 17 + 4 * q + u];
                sz += sP[(64 + o) * 17 + 4 * q + u];
            }
            sr += __shfl_xor_sync(0xffffffffu, sr, 1);
            sz += __shfl_xor_sync(0xffffffffu, sz, 1);
            sr += __shfl_xor_sync(0xffffffffu, sr, 2);
            sz += __shfl_xor_sync(0xffffffffu, sz, 2);
            float r = __fdividef(1.0f, 1.0f + __expf(-(sr + pgxr)));
            zv      = __fdividef(1.0f, 1.0f + __expf(-(sz + pgxz)));
            hv = sH[rb * 256 + j0 + rc];
            float rh = r * hv;
            st_cluster_f32(hA0 + 2048u, rh);
            st_cluster_f32(hA1 + 2048u, rh);
        }
        cluster_arrive();
        cluster_wait();

        // ---- phase B: h-tilde matvec over sRH ----
        {
            ull aH0 = 0, aH1 = 0;
            #pragma unroll
            for (int u = 0; u < 8; u++) {
                int k = k0 + 2 * u;
                ull wh = ((const ull*)sWH)[(ks * 8 + u) * 32 + c];
                ull r0 = *(const ull*)&sRH[0 * 256 + k];
                ull r1 = *(const ull*)&sRH[1 * 256 + k];
                aH0 = f2fma(wh, r0, aH0);
                aH1 = f2fma(wh, r1, aH1);
            }
            sP[(0 * 32 + c) * 17 + ks] = f2sum(aH0);   // rows 0..63
            sP[(1 * 32 + c) * 17 + ks] = f2sum(aH1);
        }
        __syncthreads();

        float hn = 0.0f;
        if (tid < 256) {
            float sh = 0.f;
            #pragma unroll
            for (int u = 0; u < 4; u++) sh += sP[o * 17 + 4 * q + u];
            sh += __shfl_xor_sync(0xffffffffu, sh, 1);
            sh += __shfl_xor_sync(0xffffffffu, sh, 2);
            float e  = __expf(2.0f * (sh + pgxh));
            float ht = 1.0f - __fdividef(2.0f, e + 1.0f);
            hn = hv + zv * (ht - hv);
            st_cluster_f32(hA0, hn);
            st_cluster_f32(hA1, hn);
        }
        cluster_arrive();
        // ---- hidden work in the arrive->wait gap ----
        if (tid < 256) {
            if (q == 0) {
                g_hs[((size_t)t * NB + (b0 + rb)) * NH + j0 + rc] = hn;
                if (t == SQ - 1) hlast[(size_t)(b0 + rb) * NH + j0 + rc] = hn;
            }
            size_t onext = (size_t)((t + 1 < SQ) ? t + 1 : t) * NH;
            pgxr = gx_base[onext];
            pgxz = gx_base[plane + onext];
            pgxh = gx_base[2 * plane + onext];
        }
        cluster_wait();
    }
}

// =====================================================================
extern "C" void kernel_launch(void* const* d_in, const int* in_sizes, int n_in,
                              void* d_out, int out_size) {
    const float* x   = (const float*)d_in[0];
    const float* Wr  = (const float*)d_in[1];
    const float* br  = (const float*)d_in[2];
    const float* Wz  = (const float*)d_in[3];
    const float* bz  = (const float*)d_in[4];
    const float* Wh  = (const float*)d_in[5];
    const float* bh  = (const float*)d_in[6];
    const float* Wfc = (const float*)d_in[7];
    const float* bfc = (const float*)d_in[8];

    float* out   = (float*)d_out;                   // [B, S, O]
    float* hlast = out + (size_t)NB * SQ * NO;      // [B, H]

    cudaFuncSetAttribute(gru_rec, cudaFuncAttributeMaxDynamicSharedMemorySize,
                         P2_SMEM_BYTES);

    // Launch-slot padding: 2 harness launches + 2 dummies -> gru_rec at #6.
    dummy_k<<<1, 32>>>(1);
    dummy_k<<<1, 32>>>(2);

    gemm_pre<<<dim3((NB * SQ) / 64, NH / 64, 3), 256>>>(x, Wr, Wz, Wh, br, bz, bh);
    gru_rec<<<(NB / CB) * 8, 512, P2_SMEM_BYTES>>>(Wr, Wz, Wh, hlast);
    gemm_fc<<<dim3((SQ * NB) / 64, NO / 64), 256>>>(Wfc, bfc, out);
}